// round 10
// baseline (speedup 1.0000x reference)
#include <cuda_runtime.h>
#include <cuda_fp16.h>
#include <cstdint>

// Problem dims (fixed by reference setup_inputs)
#define BB   64
#define NN   1024
#define EE   8
#define OO   32
#define II   64
#define EO   256
#define NEO  (NN*EO)
#define CH   16

// ---------------------------------------------------------------------------
// Scratch (device globals; no allocation allowed)
// ---------------------------------------------------------------------------
__device__ __half g_u_hat[(size_t)BB * NN * EO];   // 32 MB [b][n][eo]
__device__ float  g_spart[CH * BB * EO];           // 1 MB  [chunk][b][eo]
__device__ float  g_b[BB * NN * EE];               // logits [b][n][e]

// ---------------------------------------------------------------------------
// PTX helpers (sm_90-level only; tcgen05 rejected by this harness's target)
// ---------------------------------------------------------------------------
__device__ __forceinline__ uint32_t smem_u32(const void* p) {
    uint32_t a;
    asm("{ .reg .u64 t; cvta.to.shared.u64 t, %1; cvt.u32.u64 %0, t; }"
        : "=r"(a) : "l"(p));
    return a;
}
#define MBAR_INIT(a, c) \
    asm volatile("mbarrier.init.shared.b64 [%0], %1;" :: "r"(a), "r"(c) : "memory")
#define MBAR_EXPECT(a, bytes) \
    asm volatile("mbarrier.arrive.expect_tx.shared.b64 _, [%0], %1;" \
                 :: "r"(a), "r"(bytes) : "memory")
#define BULK_G2S(dst, src, bytes, mbar) \
    asm volatile("cp.async.bulk.shared::cta.global.mbarrier::complete_tx::bytes " \
                 "[%0], [%1], %2, [%3];" \
                 :: "r"(dst), "l"(src), "r"(bytes), "r"(mbar) : "memory")
#define MBAR_WAIT(mbar, ph) do { \
    asm volatile("{\n\t.reg .pred P1;\n\tWL_%=:\n\t" \
        "mbarrier.try_wait.parity.acquire.cta.shared::cta.b64 P1, [%0], %1, 0x989680;\n\t" \
        "@P1 bra.uni WD_%=;\n\tbra.uni WL_%=;\n\tWD_%=:\n\t}" \
        :: "r"((uint32_t)(mbar)), "r"((uint32_t)(ph)) : "memory"); } while (0)

// fp32x2 packed FMA (PTX-only; ptxas never auto-fuses FFMA2)
__device__ __forceinline__ void ffma2(unsigned long long& d,
                                      unsigned long long a,
                                      unsigned long long b) {
    asm("fma.rn.f32x2 %0, %1, %2, %0;" : "+l"(d) : "l"(a), "l"(b));
}
__device__ __forceinline__ float2 asf2(unsigned long long v) {
    union { unsigned long long u; float2 f; } c; c.u = v; return c.f;
}
// pack two floats into f16x2 with `lo` in the low half (memory-first elem)
__device__ __forceinline__ unsigned pack_f16(float lo, float hi) {
    unsigned r;
    asm("cvt.rn.f16x2.f32 %0, %1, %2;" : "=r"(r) : "f"(hi), "f"(lo));
    return r;
}

// ---------------------------------------------------------------------------
// Kernel 1: u_hat[b,n,eo] = sum_i W[n,eo,i] * u[b,n,i]   (fp16 output)
// Proven round-6 FFMA2 kernel (unchanged).
// ---------------------------------------------------------------------------
#define SW_FLOATS  (64*256)
#define SUD_FLOATS (64*128)
#define GEMM_SMEM_BYTES ((SW_FLOATS + SUD_FLOATS) * 4)

__global__ __launch_bounds__(256, 2)
void gemm_kernel(const float* __restrict__ u, const float* __restrict__ W) {
    extern __shared__ float smem[];
    float* sW  = smem;                 // [64][256] swizzled
    float* sUd = smem + SW_FLOATS;     // [64][128] dup'd

    const int n = blockIdx.x;
    const int t = threadIdx.x;
    const int w = t >> 5;
    const int l = t & 31;

    {
        const float4* wg4 = (const float4*)(W + (size_t)n * (EO * II));
        #pragma unroll
        for (int it = 0; it < 16; ++it) {
            int idx = t + it * 256;
            int eo  = idx >> 4;
            int kf4 = idx & 15;
            float4 v = wg4[idx];
            int col  = eo ^ ((kf4 & 7) << 2);
            float* p = &sW[(kf4 * 4) * 256 + col];
            p[0]   = v.x;
            p[256] = v.y;
            p[512] = v.z;
            p[768] = v.w;
        }
    }
    {
        const int b  = t >> 2;
        const int fq = t & 3;
        const float4* ug4 = (const float4*)(u + ((size_t)b * NN + n) * II);
        float2* sUd2 = (float2*)sUd;
        #pragma unroll
        for (int i = 0; i < 4; ++i) {
            int f = fq * 4 + i;
            float4 v = ug4[f];
            int k0 = f * 4;
            sUd2[(k0 + 0) * 64 + b] = make_float2(v.x, v.x);
            sUd2[(k0 + 1) * 64 + b] = make_float2(v.y, v.y);
            sUd2[(k0 + 2) * 64 + b] = make_float2(v.z, v.z);
            sUd2[(k0 + 3) * 64 + b] = make_float2(v.w, v.w);
        }
    }
    __syncthreads();

    unsigned long long acc[8][4];
    #pragma unroll
    for (int r = 0; r < 8; ++r)
        #pragma unroll
        for (int p = 0; p < 4; ++p) acc[r][p] = 0ULL;

    const float* ubase = &sUd[w * 16];

    #pragma unroll 4
    for (int k4 = 0; k4 < 16; ++k4) {
        const int X4 = (k4 & 7) << 2;
        const float* wbase = &sW[(4 * l) ^ X4];
        #pragma unroll
        for (int j = 0; j < 4; ++j) {
            const int k = k4 * 4 + j;
            const ulonglong2 w0 = *(const ulonglong2*)&wbase[k * 256];
            const ulonglong2 w1 = *(const ulonglong2*)&wbase[k * 256 + 128];
            const ulonglong2* ub = (const ulonglong2*)&ubase[k * 128];
            const ulonglong2 u0 = ub[0], u1 = ub[1], u2 = ub[2], u3 = ub[3];

            ffma2(acc[0][0], u0.x, w0.x); ffma2(acc[0][1], u0.x, w0.y);
            ffma2(acc[0][2], u0.x, w1.x); ffma2(acc[0][3], u0.x, w1.y);
            ffma2(acc[1][0], u0.y, w0.x); ffma2(acc[1][1], u0.y, w0.y);
            ffma2(acc[1][2], u0.y, w1.x); ffma2(acc[1][3], u0.y, w1.y);
            ffma2(acc[2][0], u1.x, w0.x); ffma2(acc[2][1], u1.x, w0.y);
            ffma2(acc[2][2], u1.x, w1.x); ffma2(acc[2][3], u1.x, w1.y);
            ffma2(acc[3][0], u1.y, w0.x); ffma2(acc[3][1], u1.y, w0.y);
            ffma2(acc[3][2], u1.y, w1.x); ffma2(acc[3][3], u1.y, w1.y);
            ffma2(acc[4][0], u2.x, w0.x); ffma2(acc[4][1], u2.x, w0.y);
            ffma2(acc[4][2], u2.x, w1.x); ffma2(acc[4][3], u2.x, w1.y);
            ffma2(acc[5][0], u2.y, w0.x); ffma2(acc[5][1], u2.y, w0.y);
            ffma2(acc[5][2], u2.y, w1.x); ffma2(acc[5][3], u2.y, w1.y);
            ffma2(acc[6][0], u3.x, w0.x); ffma2(acc[6][1], u3.x, w0.y);
            ffma2(acc[6][2], u3.x, w1.x); ffma2(acc[6][3], u3.x, w1.y);
            ffma2(acc[7][0], u3.y, w0.x); ffma2(acc[7][1], u3.y, w0.y);
            ffma2(acc[7][2], u3.y, w1.x); ffma2(acc[7][3], u3.y, w1.y);
        }
    }

    __half* outp = g_u_hat + (size_t)n * EO + 4 * l;
    #pragma unroll
    for (int r = 0; r < 8; ++r) {
        float2 p0 = asf2(acc[r][0]), p1 = asf2(acc[r][1]);
        float2 p2 = asf2(acc[r][2]), p3 = asf2(acc[r][3]);
        __half* pp = outp + (size_t)(w * 8 + r) * NEO;
        uint2 lo, hi;
        lo.x = pack_f16(p0.x, p0.y); lo.y = pack_f16(p1.x, p1.y);
        hi.x = pack_f16(p2.x, p2.y); hi.y = pack_f16(p3.x, p3.y);
        *(uint2*)pp         = lo;
        *(uint2*)(pp + 128) = hi;
    }
}

// ---------------------------------------------------------------------------
// Kernel 2: s0 partial via TMA bulk staging (proven, ~4us).
// ---------------------------------------------------------------------------
__global__ __launch_bounds__(256)
void reduce_s0_kernel() {
    __shared__ __align__(128) char s_tile[64 * 512];
    __shared__ float s_sh[8 * EO];
    __shared__ __align__(8) uint64_t s_mbar;
    const int b = blockIdx.x >> 4;
    const int chunk = blockIdx.x & 15;
    const int t = threadIdx.x, w = t >> 5, l = t & 31;
    const uint32_t mbar = smem_u32(&s_mbar);

    if (t == 0) MBAR_INIT(mbar, 1);
    __syncthreads();
    if (t == 0) {
        const __half* gp = g_u_hat + (size_t)b * NEO + (size_t)(chunk * 64) * EO;
        uint64_t ga = (uint64_t)__cvta_generic_to_global((void*)gp);
        MBAR_EXPECT(mbar, 32768);
        BULK_G2S(smem_u32(s_tile), ga, 32768, mbar);
    }
    MBAR_WAIT(mbar, 0);

    float acc[8];
    #pragma unroll
    for (int i = 0; i < 8; ++i) acc[i] = 0.f;
    #pragma unroll
    for (int j = 0; j < 8; ++j) {
        uint4 r = *(const uint4*)(s_tile + (w * 8 + j) * 512 + l * 16);
        float2 f;
        f = __half22float2(*(const __half2*)&r.x); acc[0] += f.x; acc[1] += f.y;
        f = __half22float2(*(const __half2*)&r.y); acc[2] += f.x; acc[3] += f.y;
        f = __half22float2(*(const __half2*)&r.z); acc[4] += f.x; acc[5] += f.y;
        f = __half22float2(*(const __half2*)&r.w); acc[6] += f.x; acc[7] += f.y;
    }
    float* sw = &s_sh[w * EO + 8 * l];
    #pragma unroll
    for (int i = 0; i < 8; ++i) sw[i] = acc[i];
    __syncthreads();
    float sum = 0.f;
    #pragma unroll
    for (int ww = 0; ww < 8; ++ww) sum += s_sh[ww * EO + t];
    g_spart[chunk * (BB * EO) + b * EO + t] = sum * 0.125f;
}

// ---------------------------------------------------------------------------
// Kernel 3 (final): squash partial sums -> d_out
// ---------------------------------------------------------------------------
__global__ __launch_bounds__(256)
void squash_final_kernel(float* __restrict__ out) {
    const int t = threadIdx.x, w = t >> 5, l = t & 31;
    const int idx = (blockIdx.x * 8 + w) * 32 + l;
    float x = 0.f;
    #pragma unroll
    for (int c = 0; c < CH; ++c) x += g_spart[c * (BB * EO) + idx];
    float n2 = x * x;
    n2 += __shfl_xor_sync(0xffffffffu, n2, 1);
    n2 += __shfl_xor_sync(0xffffffffu, n2, 2);
    n2 += __shfl_xor_sync(0xffffffffu, n2, 4);
    n2 += __shfl_xor_sync(0xffffffffu, n2, 8);
    n2 += __shfl_xor_sync(0xffffffffu, n2, 16);
    float nrm = sqrtf(n2);
    float scale = n2 / ((1.f + n2) * (nrm + 1e-8f));
    out[idx] = x * scale;
}

// ---------------------------------------------------------------------------
// Kernel 4/5: shuffle-light routing iteration.
// Phase A: lane owns (n,e): lane-local dot over o (v[e] in 32 regs, chunk
// permutation jj=(j+e+(e>>2))&3 keeps lane-octets bank-conflict-free);
// softmax over E = 6 shfl per 4 n (xor 1,2,4 within octets). c -> SMEM.
// Phase B: thread owns eo-pair; half2 loads (warp spans 128B, conflict-free);
// c broadcast; zero shuffles.
// ---------------------------------------------------------------------------
template <int ITER>
__global__ __launch_bounds__(256)
void routing_kernel() {
    __shared__ __align__(128) char s_tile[64 * 512];   // 32 KB
    __shared__ float s_v[EO];                          // v[e*32+o]
    __shared__ float s_c[64 * 8];                      // c[n][e]
    __shared__ float s_ph[2 * EO];                     // phase-B halves
    __shared__ __align__(8) uint64_t s_mbar;
    const int b = blockIdx.x >> 4;
    const int chunk = blockIdx.x & 15;
    const int t = threadIdx.x, w = t >> 5, l = t & 31;
    const int e  = l & 7;
    const int nq = l >> 3;
    const uint32_t mbar = smem_u32(&s_mbar);

    if (t == 0) MBAR_INIT(mbar, 1);
    __syncthreads();
    if (t == 0) {
        const __half* gp = g_u_hat + (size_t)b * NEO + (size_t)(chunk * 64) * EO;
        uint64_t ga = (uint64_t)__cvta_generic_to_global((void*)gp);
        MBAR_EXPECT(mbar, 32768);
        BULK_G2S(smem_u32(s_tile), ga, 32768, mbar);
    }

    // prior logits for this lane's two (n,e) tasks (overlaps TMA)
    float* gb = g_b + b * (NN * EE) + (chunk * 64) * EE;
    float bpre[2];
    if (ITER == 2) {
        #pragma unroll
        for (int r = 0; r < 2; ++r)
            bpre[r] = gb[(w * 8 + r * 4 + nq) * 8 + e];
    }

    // prologue: v = squash(sum_c spart)  (overlaps TMA)
    {
        float x = 0.f;
        #pragma unroll
        for (int c = 0; c < CH; ++c) x += g_spart[c * (BB * EO) + b * EO + t];
        float n2 = x * x;
        n2 += __shfl_xor_sync(0xffffffffu, n2, 1);
        n2 += __shfl_xor_sync(0xffffffffu, n2, 2);
        n2 += __shfl_xor_sync(0xffffffffu, n2, 4);
        n2 += __shfl_xor_sync(0xffffffffu, n2, 8);
        n2 += __shfl_xor_sync(0xffffffffu, n2, 16);
        float nrm = sqrtf(n2);
        float scale = n2 / ((1.f + n2) * (nrm + 1e-8f));
        s_v[t] = x * scale;
    }
    __syncthreads();

    // preload v[e] into registers, permuted to match the u-chunk order
    float vv[4][8];
    #pragma unroll
    for (int j = 0; j < 4; ++j) {
        const int jj = (j + e + (e >> 2)) & 3;
        const float* vp = s_v + e * 32 + jj * 8;
        float4 a = *(const float4*)vp;
        float4 bq = *(const float4*)(vp + 4);
        vv[j][0] = a.x;  vv[j][1] = a.y;  vv[j][2] = a.z;  vv[j][3] = a.w;
        vv[j][4] = bq.x; vv[j][5] = bq.y; vv[j][6] = bq.z; vv[j][7] = bq.w;
    }

    MBAR_WAIT(mbar, 0);

    // ---- Phase A: dots + softmax + c
    #pragma unroll
    for (int r = 0; r < 2; ++r) {
        const int n = w * 8 + r * 4 + nq;
        const char* urow = s_tile + n * 512 + e * 64;
        float a0 = 0.f, a1 = 0.f;
        #pragma unroll
        for (int j = 0; j < 4; ++j) {
            const int jj = (j + e + (e >> 2)) & 3;
            uint4 q = *(const uint4*)(urow + jj * 16);
            float2 f;
            f = __half22float2(*(const __half2*)&q.x);
            a0 += f.x * vv[j][0]; a1 += f.y * vv[j][1];
            f = __half22float2(*(const __half2*)&q.y);
            a0 += f.x * vv[j][2]; a1 += f.y * vv[j][3];
            f = __half22float2(*(const __half2*)&q.z);
            a0 += f.x * vv[j][4]; a1 += f.y * vv[j][5];
            f = __half22float2(*(const __half2*)&q.w);
            a0 += f.x * vv[j][6]; a1 += f.y * vv[j][7];
        }
        float bn = a0 + a1;
        if (ITER == 2) bn += bpre[r];
        else gb[n * 8 + e] = bn;          // b1 = uv0 (b starts at 0); coalesced

        // softmax over e (xor 1,2,4 stays within each 8-lane octet)
        float m = bn;
        m = fmaxf(m, __shfl_xor_sync(0xffffffffu, m, 1));
        m = fmaxf(m, __shfl_xor_sync(0xffffffffu, m, 2));
        m = fmaxf(m, __shfl_xor_sync(0xffffffffu, m, 4));
        float ex = __expf(bn - m);
        float sm = ex;
        sm += __shfl_xor_sync(0xffffffffu, sm, 1);
        sm += __shfl_xor_sync(0xffffffffu, sm, 2);
        sm += __shfl_xor_sync(0xffffffffu, sm, 4);
        s_c[n * 8 + e] = __fdividef(ex, sm);
    }
    __syncthreads();

    // ---- Phase B: s[eo] = sum_n c[n][e] * u_hat[n][eo]; no shuffles
    {
        const int h = t >> 7;          // n-half (0..1)
        const int p = t & 127;         // eo pair; eo = {2p, 2p+1}; e = p>>4
        float ax = 0.f, ay = 0.f;
        const char* base = s_tile + (h * 32) * 512 + p * 4;
        const float* cp = s_c + (h * 32) * 8 + (p >> 4);
        #pragma unroll 8
        for (int i = 0; i < 32; ++i) {
            float2 f = __half22float2(*(const __half2*)(base + i * 512));
            float c = cp[i * 8];
            ax += c * f.x;
            ay += c * f.y;
        }
        s_ph[h * EO + 2 * p]     = ax;
        s_ph[h * EO + 2 * p + 1] = ay;
    }
    __syncthreads();
    g_spart[chunk * (BB * EO) + b * EO + t] = s_ph[t] + s_ph[EO + t];
}

// ---------------------------------------------------------------------------
// Launch
// ---------------------------------------------------------------------------
extern "C" void kernel_launch(void* const* d_in, const int* in_sizes, int n_in,
                              void* d_out, int out_size) {
    const float* u = (const float*)d_in[0];
    const float* W = (const float*)d_in[1];
    if (n_in >= 2 && in_sizes[0] > in_sizes[1]) {  // u = 4.19M elems, W = 16.78M
        const float* tmp = u; u = W; W = tmp;
    }
    float* out = (float*)d_out;
    (void)out_size;

    cudaFuncSetAttribute(gemm_kernel,
                         cudaFuncAttributeMaxDynamicSharedMemorySize,
                         GEMM_SMEM_BYTES);

    gemm_kernel<<<NN, 256, GEMM_SMEM_BYTES>>>(u, W);   // u_hat (fp16)
    reduce_s0_kernel<<<BB * CH, 256>>>();              // s0 partials (c=1/8)
    routing_kernel<1><<<BB * CH, 256>>>();             // v0, b1, s1
    routing_kernel<2><<<BB * CH, 256>>>();             // v1, b2, s2
    squash_final_kernel<<<64, 256>>>(out);             // v2 -> d_out
}